// round 5
// baseline (speedup 1.0000x reference)
#include <cuda_runtime.h>
#include <cuda_bf16.h>
#include <cstdint>

#define BBATCH 16
#define CCH 512
#define M_PIX (BBATCH*64*64)     // 65536
#define NPROJ 384
#define DK 64
#define DV 256
#define NKV 1024
#define NQ  4096

// ---------------- scratch (device globals) ----------------
__device__ __align__(256) __nv_bfloat16 g_xb   [M_PIX * CCH];       // x in bf16
__device__ __align__(256) __nv_bfloat16 g_projb[M_PIX * NPROJ];     // theta|phi|g bf16
__device__ __align__(256) __nv_bfloat16 g_phi  [BBATCH * NKV * DK]; // pooled phi [kv][d]
__device__ __align__(256) __nv_bfloat16 g_gT   [BBATCH * DV * NKV]; // pooled g^T [d][kv]
__device__ __align__(256) __nv_bfloat16 g_S    [(size_t)M_PIX * NKV]; // exp(logits)
__device__ __align__(256) __nv_bfloat16 g_ag   [M_PIX * DV];        // attn out bf16
__device__ __align__(256) __nv_bfloat16 g_wcatT[NPROJ * CCH];       // proj weights^T
__device__ __align__(256) __nv_bfloat16 g_woT  [CCH * DV];          // w_o^T
__device__ float g_bcat[NPROJ];

// ---------------- helpers ----------------
__device__ __forceinline__ uint32_t smem_u32(const void* p) {
    uint32_t a;
    asm("{ .reg .u64 t; cvta.to.shared.u64 t, %1; cvt.u32.u64 %0, t; }" : "=r"(a) : "l"(p));
    return a;
}
#define SWZ(o) ((o) ^ (((o) >> 3) & 0x70))

__device__ __forceinline__ void ldsm_x4(uint32_t* r, uint32_t a) {
    asm volatile("ldmatrix.sync.aligned.m8n8.x4.shared.b16 {%0,%1,%2,%3}, [%4];"
        : "=r"(r[0]), "=r"(r[1]), "=r"(r[2]), "=r"(r[3]) : "r"(a));
}
__device__ __forceinline__ void mma16816(float* d, const uint32_t* a, uint32_t b0, uint32_t b1) {
    asm volatile("mma.sync.aligned.m16n8k16.row.col.f32.bf16.bf16.f32 "
        "{%0,%1,%2,%3}, {%4,%5,%6,%7}, {%8,%9}, {%0,%1,%2,%3};"
        : "+f"(d[0]), "+f"(d[1]), "+f"(d[2]), "+f"(d[3])
        : "r"(a[0]), "r"(a[1]), "r"(a[2]), "r"(a[3]), "r"(b0), "r"(b1));
}
__device__ __forceinline__ void cp16(uint32_t sa, const void* ga) {
    asm volatile("cp.async.cg.shared.global [%0], [%1], 16;" :: "r"(sa), "l"(ga));
}
#define CP_COMMIT() asm volatile("cp.async.commit_group;" ::: "memory")
#define CP_WAIT(n)  asm volatile("cp.async.wait_group %0;" :: "n"(n) : "memory")

// load [ROWS x 64] bf16 tile (row stride ld) into swizzled SMEM via cp.async
template <int ROWS>
__device__ __forceinline__ void load_tile_async(const __nv_bfloat16* __restrict__ src,
                                                size_t ld, uint32_t sbase, int tid) {
#pragma unroll
    for (int t = 0; t < ROWS / 32; t++) {
        int i = tid + t * 256;
        int row = i >> 3, c = i & 7;
        cp16(sbase + SWZ(row * 128 + c * 16), src + (size_t)row * ld + c * 8);
    }
}

// ------------- 128x128-tile bf16 HMMA GEMM, fp32 accum, 3-stage cp.async ----
// D[m0:+128, n0:+128] = A[m,:] @ B[n,:]^T   (A: MxK k-major; B: NxK k-major)
// MODE 0: bf16 out + fp32 bias;  MODE 4: bf16 out = exp(D)
template <int MODE>
__global__ void __launch_bounds__(256, 2)
gemm128(const __nv_bfloat16* __restrict__ A, int lda,
        const __nv_bfloat16* __restrict__ B, int ldb, size_t bstride,
        int K,
        __nv_bfloat16* __restrict__ outb, int ldo,
        const float* __restrict__ bias) {
    extern __shared__ char sm[];
    uint32_t base = smem_u32(sm);
    const uint32_t a_su[3] = {base, base + 16384, base + 32768};
    const uint32_t b_su[3] = {base + 49152, base + 65536, base + 81920};

    int tid = threadIdx.x, wid = tid >> 5, lane = tid & 31;
    int m0 = blockIdx.y * 128, n0 = blockIdx.x * 128;
    int wm = wid & 3, wn = wid >> 2;
    int lr = lane & 15, lc = lane >> 4;

    const __nv_bfloat16* Ab = A + (size_t)m0 * lda;
    const __nv_bfloat16* Bb = B + (size_t)(m0 >> 12) * bstride + (size_t)n0 * ldb;

    float acc[2][8][4];
#pragma unroll
    for (int i = 0; i < 2; i++)
#pragma unroll
        for (int j = 0; j < 8; j++)
#pragma unroll
            for (int e = 0; e < 4; e++) acc[i][j][e] = 0.f;

    const int nc = K >> 6;
    load_tile_async<128>(Ab, (size_t)lda, a_su[0], tid);
    load_tile_async<128>(Bb, (size_t)ldb, b_su[0], tid);
    CP_COMMIT();
    if (nc > 1) {
        load_tile_async<128>(Ab + 64, (size_t)lda, a_su[1], tid);
        load_tile_async<128>(Bb + 64, (size_t)ldb, b_su[1], tid);
        CP_COMMIT();
    }

    for (int c = 0; c < nc; c++) {
        if (c + 2 <= nc) { CP_WAIT(1); } else { CP_WAIT(0); }
        __syncthreads();

        int buf = c % 3;
        uint32_t abase = a_su[buf], bbase = b_su[buf];
#pragma unroll
        for (int k16 = 0; k16 < 4; k16++) {
            uint32_t af[2][4];
#pragma unroll
            for (int mt = 0; mt < 2; mt++)
                ldsm_x4(af[mt], abase + SWZ((wm * 32 + mt * 16 + lr) * 128 + k16 * 32 + lc * 16));
            uint32_t bf4[4][4];
#pragma unroll
            for (int nt2 = 0; nt2 < 4; nt2++)
                ldsm_x4(bf4[nt2], bbase + SWZ((wn * 64 + nt2 * 16 + lr) * 128 + k16 * 32 + lc * 16));
#pragma unroll
            for (int mt = 0; mt < 2; mt++)
#pragma unroll
                for (int nt = 0; nt < 8; nt++)
                    mma16816(acc[mt][nt], af[mt], bf4[nt >> 1][nt & 1], bf4[nt >> 1][2 + (nt & 1)]);
        }

        if (c + 2 < nc) {
            int nb = (c + 2) % 3;
            load_tile_async<128>(Ab + (c + 2) * 64, (size_t)lda, a_su[nb], tid);
            load_tile_async<128>(Bb + (c + 2) * 64, (size_t)ldb, b_su[nb], tid);
            CP_COMMIT();
        }
    }

    int r0 = m0 + wm * 32 + (lane >> 2);
    int c0 = n0 + wn * 64 + (lane & 3) * 2;
#pragma unroll
    for (int mt = 0; mt < 2; mt++) {
#pragma unroll
        for (int half = 0; half < 2; half++) {
            int row = r0 + mt * 16 + half * 8;
#pragma unroll
            for (int nt = 0; nt < 8; nt++) {
                int col = c0 + nt * 8;
                float v0 = acc[mt][nt][half * 2 + 0];
                float v1 = acc[mt][nt][half * 2 + 1];
                if (MODE == 0) { v0 += bias[col]; v1 += bias[col + 1]; }
                if (MODE == 4) { v0 = __expf(v0); v1 = __expf(v1); }
                *(__nv_bfloat162*)(outb + (size_t)row * ldo + col) =
                    __floats2bfloat162_rn(v0, v1);
            }
        }
    }
}

// ------------- 128x256-tile bf16 HMMA GEMM, warp tile 64x64 ----------------
// MODE 3: bf16 out, normalized by row sums of A (in-loop)   [PV]
// MODE 2: fp32 out = X + sig*(D+bias)                        [out proj]
template <int MODE>
__global__ void __launch_bounds__(256, 1)
gemm256(const __nv_bfloat16* __restrict__ A, int lda,
        const __nv_bfloat16* __restrict__ B, int ldb, size_t bstride,
        int K,
        __nv_bfloat16* __restrict__ outb, int ldo,
        const float* __restrict__ bias,
        const float* __restrict__ Xres, const float* __restrict__ sig,
        float* __restrict__ outf) {
    extern __shared__ char sm[];
    uint32_t base = smem_u32(sm);
    const uint32_t a_su[3] = {base, base + 16384, base + 32768};
    const uint32_t b_su[3] = {base + 49152, base + 49152 + 32768, base + 49152 + 65536};
    float* rinv_s = (float*)(sm + 147456);   // [128] (MODE 3)

    int tid = threadIdx.x, wid = tid >> 5, lane = tid & 31;
    int m0 = blockIdx.y * 128, n0 = blockIdx.x * 256;
    int wm = wid & 1, wn = wid >> 1;          // 2m x 4n warps, warp tile 64x64
    int lr = lane & 15, lc = lane >> 4;

    const __nv_bfloat16* Ab = A + (size_t)m0 * lda;
    const __nv_bfloat16* Bb = B + (size_t)(m0 >> 12) * bstride + (size_t)n0 * ldb;

    float acc[4][8][4];
#pragma unroll
    for (int i = 0; i < 4; i++)
#pragma unroll
        for (int j = 0; j < 8; j++)
#pragma unroll
            for (int e = 0; e < 4; e++) acc[i][j][e] = 0.f;

    float rsum = 0.f;
    const int nc = K >> 6;

    load_tile_async<128>(Ab, (size_t)lda, a_su[0], tid);
    load_tile_async<256>(Bb, (size_t)ldb, b_su[0], tid);
    CP_COMMIT();
    if (nc > 1) {
        load_tile_async<128>(Ab + 64, (size_t)lda, a_su[1], tid);
        load_tile_async<256>(Bb + 64, (size_t)ldb, b_su[1], tid);
        CP_COMMIT();
    }

    for (int c = 0; c < nc; c++) {
        if (c + 2 <= nc) { CP_WAIT(1); } else { CP_WAIT(0); }
        __syncthreads();

        int buf = c % 3;
        if (MODE == 3) {
            // accumulate row sums of exp(S) from the A chunk
            int row = tid >> 1, half = tid & 1;
            const char* aptr = sm + buf * 16384;
#pragma unroll
            for (int c8 = 0; c8 < 4; c8++) {
                uint4 u = *(const uint4*)(aptr + SWZ(row * 128 + half * 64 + c8 * 16));
                const __nv_bfloat162* h = (const __nv_bfloat162*)&u;
#pragma unroll
                for (int j = 0; j < 4; j++) {
                    float2 f = __bfloat1622float2(h[j]);
                    rsum += f.x + f.y;
                }
            }
        }

        uint32_t abase = a_su[buf], bbase = b_su[buf];
#pragma unroll
        for (int k16 = 0; k16 < 4; k16++) {
            uint32_t af[4][4];
#pragma unroll
            for (int mt = 0; mt < 4; mt++)
                ldsm_x4(af[mt], abase + SWZ((wm * 64 + mt * 16 + lr) * 128 + k16 * 32 + lc * 16));
            uint32_t bf4[4][4];
#pragma unroll
            for (int nt2 = 0; nt2 < 4; nt2++)
                ldsm_x4(bf4[nt2], bbase + SWZ((wn * 64 + nt2 * 16 + lr) * 128 + k16 * 32 + lc * 16));
#pragma unroll
            for (int mt = 0; mt < 4; mt++)
#pragma unroll
                for (int nt = 0; nt < 8; nt++)
                    mma16816(acc[mt][nt], af[mt], bf4[nt >> 1][nt & 1], bf4[nt >> 1][2 + (nt & 1)]);
        }

        if (c + 2 < nc) {
            int nb = (c + 2) % 3;
            load_tile_async<128>(Ab + (c + 2) * 64, (size_t)lda, a_su[nb], tid);
            load_tile_async<256>(Bb + (c + 2) * 64, (size_t)ldb, b_su[nb], tid);
            CP_COMMIT();
        }
    }

    if (MODE == 3) {
        rsum += __shfl_xor_sync(0xffffffffu, rsum, 1);
        if ((tid & 1) == 0) rinv_s[tid >> 1] = 1.f / rsum;
        __syncthreads();
    }

    // epilogue: warp covers rows [wm*64, +64), cols [wn*64, +64)
    int r0 = m0 + wm * 64 + (lane >> 2);
    int c0 = n0 + wn * 64 + (lane & 3) * 2;
    float s = 0.f;
    if (MODE == 2) s = sig[0];
#pragma unroll
    for (int mt = 0; mt < 4; mt++) {
#pragma unroll
        for (int half = 0; half < 2; half++) {
            int row = r0 + mt * 16 + half * 8;
            float rscale = 1.f;
            if (MODE == 3) rscale = rinv_s[wm * 64 + (lane >> 2) + mt * 16 + half * 8];
#pragma unroll
            for (int nt = 0; nt < 8; nt++) {
                int col = c0 + nt * 8;
                float v0 = acc[mt][nt][half * 2 + 0];
                float v1 = acc[mt][nt][half * 2 + 1];
                if (MODE == 3) {
                    v0 *= rscale; v1 *= rscale;
                    *(__nv_bfloat162*)(outb + (size_t)row * ldo + col) =
                        __floats2bfloat162_rn(v0, v1);
                }
                if (MODE == 2) {
                    const float* xr = Xres + (size_t)row * CCH + col;
                    float2 xv = *(const float2*)xr;
                    float2 o;
                    o.x = xv.x + s * (v0 + bias[col]);
                    o.y = xv.y + s * (v1 + bias[col + 1]);
                    *(float2*)(outf + (size_t)row * CCH + col) = o;
                }
            }
        }
    }
}

// ---------------- small kernels ----------------
__global__ void pack_kernel(const float* __restrict__ wt, const float* __restrict__ wp,
                            const float* __restrict__ wg, const float* __restrict__ bt,
                            const float* __restrict__ bp, const float* __restrict__ bg,
                            const float* __restrict__ wo) {
    int idx = blockIdx.x * blockDim.x + threadIdx.x;
    if (idx < NPROJ * CCH) {           // wcatT[n][k] = w(k, n)
        int n = idx / CCH, k = idx - n * CCH;
        float v;
        if (n < 64)       v = wt[k * 64 + n];
        else if (n < 128) v = wp[k * 64 + (n - 64)];
        else              v = wg[k * 256 + (n - 128)];
        g_wcatT[idx] = __float2bfloat16(v);
    }
    if (idx < CCH * DV) {              // woT[n][k] = wo[k][n]
        int n = idx / DV, k = idx - n * DV;
        g_woT[idx] = __float2bfloat16(wo[k * CCH + n]);
    }
    if (idx < NPROJ) {
        float v;
        if (idx < 64)       v = bt[idx];
        else if (idx < 128) v = bp[idx - 64];
        else                v = bg[idx - 128];
        g_bcat[idx] = v;
    }
}

__global__ void xconv_kernel(const float* __restrict__ x) {
    int i = blockIdx.x * blockDim.x + threadIdx.x;  // 8 elems each
    if (i >= M_PIX * CCH / 8) return;
    float4 a = *(const float4*)(x + (size_t)i * 8);
    float4 b = *(const float4*)(x + (size_t)i * 8 + 4);
    __nv_bfloat162 h[4];
    h[0] = __floats2bfloat162_rn(a.x, a.y);
    h[1] = __floats2bfloat162_rn(a.z, a.w);
    h[2] = __floats2bfloat162_rn(b.x, b.y);
    h[3] = __floats2bfloat162_rn(b.z, b.w);
    *(uint4*)(g_xb + (size_t)i * 8) = *(uint4*)h;
}

__global__ void pool_phi_kernel() {
    int i = blockIdx.x * blockDim.x + threadIdx.x;
    if (i >= BBATCH * NKV * 8) return;   // 8 groups of 8 channels
    int pp = i >> 3, c8 = i & 7;
    int b = pp >> 10, idx = pp & 1023;
    int h2 = idx >> 5, w2 = idx & 31;
    size_t p = (size_t)((b * 64 + h2 * 2) * 64 + w2 * 2);
    const __nv_bfloat16* src = g_projb + p * NPROJ + 64 + c8 * 8;
    uint4 u0 = *(const uint4*)(src);
    uint4 u1 = *(const uint4*)(src + NPROJ);
    uint4 u2 = *(const uint4*)(src + 64 * NPROJ);
    uint4 u3 = *(const uint4*)(src + 65 * NPROJ);
    __nv_bfloat162* h0 = (__nv_bfloat162*)&u0; __nv_bfloat162* h1 = (__nv_bfloat162*)&u1;
    __nv_bfloat162* h2v = (__nv_bfloat162*)&u2; __nv_bfloat162* h3 = (__nv_bfloat162*)&u3;
    __nv_bfloat162 o[4];
#pragma unroll
    for (int j = 0; j < 4; j++)
        o[j] = __hmax2(__hmax2(h0[j], h1[j]), __hmax2(h2v[j], h3[j]));
    *(uint4*)(g_phi + (size_t)pp * DK + c8 * 8) = *(uint4*)o;
}

__global__ void pool_gt_kernel() {   // pooled g, transposed to [b][d][kv]
    __shared__ __nv_bfloat16 ts[64][65];
    int tid = threadIdx.x;
    int d0 = blockIdx.x * 64, kv0 = blockIdx.y * 64, b = blockIdx.z;
#pragma unroll
    for (int e = 0; e < 16; e++) {
        int idx = tid + e * 256;
        int kvl = idx >> 6, dl = idx & 63;
        int kv = kv0 + kvl;
        int h2 = kv >> 5, w2 = kv & 31;
        size_t p = (size_t)((b * 64 + h2 * 2) * 64 + w2 * 2);
        const __nv_bfloat16* src = g_projb + p * NPROJ + 128 + d0 + dl;
        __nv_bfloat16 v = __hmax(__hmax(src[0], src[NPROJ]),
                                 __hmax(src[64 * NPROJ], src[65 * NPROJ]));
        ts[kvl][dl] = v;
    }
    __syncthreads();
#pragma unroll
    for (int e = 0; e < 16; e++) {
        int idx = tid + e * 256;
        int dl = idx >> 6, kk = idx & 63;
        g_gT[((size_t)b * DV + d0 + dl) * NKV + kv0 + kk] = ts[kk][dl];
    }
}

// ---------------- launcher ----------------
extern "C" void kernel_launch(void* const* d_in, const int* in_sizes, int n_in,
                              void* d_out, int out_size) {
    const float* x       = (const float*)d_in[0];
    const float* w_theta = (const float*)d_in[1];
    const float* b_theta = (const float*)d_in[2];
    const float* w_phi   = (const float*)d_in[3];
    const float* b_phi   = (const float*)d_in[4];
    const float* w_g     = (const float*)d_in[5];
    const float* b_g     = (const float*)d_in[6];
    const float* w_o     = (const float*)d_in[7];
    const float* b_o     = (const float*)d_in[8];
    const float* sigma   = (const float*)d_in[9];
    float* out = (float*)d_out;

    const int SMEM128 = 98304;
    const int SMEM256 = 147456 + 512;
    cudaFuncSetAttribute((const void*)gemm128<0>, cudaFuncAttributeMaxDynamicSharedMemorySize, SMEM128);
    cudaFuncSetAttribute((const void*)gemm128<4>, cudaFuncAttributeMaxDynamicSharedMemorySize, SMEM128);
    cudaFuncSetAttribute((const void*)gemm256<2>, cudaFuncAttributeMaxDynamicSharedMemorySize, SMEM256);
    cudaFuncSetAttribute((const void*)gemm256<3>, cudaFuncAttributeMaxDynamicSharedMemorySize, SMEM256);

    __nv_bfloat16 *xb, *projb, *phi, *gT, *S, *ag, *wcatT, *woT;
    float* bcat;
    cudaGetSymbolAddress((void**)&xb, g_xb);       cudaGetSymbolAddress((void**)&projb, g_projb);
    cudaGetSymbolAddress((void**)&phi, g_phi);     cudaGetSymbolAddress((void**)&gT, g_gT);
    cudaGetSymbolAddress((void**)&S, g_S);         cudaGetSymbolAddress((void**)&ag, g_ag);
    cudaGetSymbolAddress((void**)&wcatT, g_wcatT); cudaGetSymbolAddress((void**)&woT, g_woT);
    cudaGetSymbolAddress((void**)&bcat, g_bcat);

    pack_kernel<<<(NPROJ * CCH + 255) / 256, 256>>>(w_theta, w_phi, w_g,
                                                    b_theta, b_phi, b_g, w_o);
    xconv_kernel<<<M_PIX * CCH / 8 / 256, 256>>>(x);

    // proj: [65536, 384] = xb[65536,512] @ wcatT[384,512]^T, +bias
    gemm128<0><<<dim3(NPROJ / 128, M_PIX / 128), 256, SMEM128>>>(
        xb, CCH, wcatT, CCH, 0, CCH, projb, NPROJ, bcat);

    pool_phi_kernel<<<(BBATCH * NKV * 8 + 255) / 256, 256>>>();
    pool_gt_kernel<<<dim3(DV / 64, NKV / 64, BBATCH), 256>>>();

    // S_exp: per batch [4096, 1024] = exp(theta[4096,64] @ phi[1024,64]^T)
    gemm128<4><<<dim3(NKV / 128, M_PIX / 128), 256, SMEM128>>>(
        projb, NPROJ, phi, DK, (size_t)NKV * DK, DK, S, NKV, nullptr);

    // PV: per batch [4096, 256] = (S_exp/rowsum)[4096,1024] @ gT[256,1024]^T
    gemm256<3><<<dim3(1, M_PIX / 128), 256, SMEM256>>>(
        S, NKV, gT, NKV, (size_t)DV * NKV, NKV, ag, DV, nullptr, nullptr, nullptr, nullptr);

    // out: [65536, 512] = x + sigma * (ag[65536,256] @ woT[512,256]^T + b_o)
    gemm256<2><<<dim3(CCH / 256, M_PIX / 128), 256, SMEM256>>>(
        ag, DV, woT, DV, 0, DV, nullptr, 0, b_o, x, sigma, out);
}

// round 6
// speedup vs baseline: 1.1509x; 1.1509x over previous
#include <cuda_runtime.h>
#include <cuda_bf16.h>
#include <cstdint>

#define BBATCH 16
#define CCH 512
#define M_PIX (BBATCH*64*64)     // 65536
#define NPROJ 384
#define DK 64
#define DV 256
#define NKV 1024
#define NQ  4096

// ---------------- scratch (device globals) ----------------
__device__ __align__(256) __nv_bfloat16 g_xb   [M_PIX * CCH];       // x in bf16
__device__ __align__(256) __nv_bfloat16 g_projb[M_PIX * NPROJ];     // theta|phi|g bf16
__device__ __align__(256) __nv_bfloat16 g_phi  [BBATCH * NKV * DK]; // pooled phi [kv][d]
__device__ __align__(256) __nv_bfloat16 g_gT   [BBATCH * DV * NKV]; // pooled g^T [d][kv]
__device__ __align__(256) __nv_bfloat16 g_ag   [M_PIX * DV];        // attn out bf16
__device__ __align__(256) __nv_bfloat16 g_wcatT[NPROJ * CCH];       // proj weights^T
__device__ __align__(256) __nv_bfloat16 g_woT  [CCH * DV];          // w_o^T
__device__ float g_bcat[NPROJ];

// ---------------- helpers ----------------
__device__ __forceinline__ uint32_t smem_u32(const void* p) {
    uint32_t a;
    asm("{ .reg .u64 t; cvta.to.shared.u64 t, %1; cvt.u32.u64 %0, t; }" : "=r"(a) : "l"(p));
    return a;
}
#define SWZ(o) ((o) ^ (((o) >> 3) & 0x70))

__device__ __forceinline__ void ldsm_x4(uint32_t* r, uint32_t a) {
    asm volatile("ldmatrix.sync.aligned.m8n8.x4.shared.b16 {%0,%1,%2,%3}, [%4];"
        : "=r"(r[0]), "=r"(r[1]), "=r"(r[2]), "=r"(r[3]) : "r"(a));
}
__device__ __forceinline__ void mma16816(float* d, const uint32_t* a, uint32_t b0, uint32_t b1) {
    asm volatile("mma.sync.aligned.m16n8k16.row.col.f32.bf16.bf16.f32 "
        "{%0,%1,%2,%3}, {%4,%5,%6,%7}, {%8,%9}, {%0,%1,%2,%3};"
        : "+f"(d[0]), "+f"(d[1]), "+f"(d[2]), "+f"(d[3])
        : "r"(a[0]), "r"(a[1]), "r"(a[2]), "r"(a[3]), "r"(b0), "r"(b1));
}
__device__ __forceinline__ void cp16(uint32_t sa, const void* ga) {
    asm volatile("cp.async.cg.shared.global [%0], [%1], 16;" :: "r"(sa), "l"(ga));
}
#define CP_COMMIT() asm volatile("cp.async.commit_group;" ::: "memory")
#define CP_WAIT(n)  asm volatile("cp.async.wait_group %0;" :: "n"(n) : "memory")

// load [ROWS x 64] bf16 tile (row stride ld) into swizzled SMEM via cp.async
template <int ROWS>
__device__ __forceinline__ void load_tile_async(const __nv_bfloat16* __restrict__ src,
                                                size_t ld, uint32_t sbase, int tid) {
#pragma unroll
    for (int t = 0; t < ROWS / 32; t++) {
        int i = tid + t * 256;
        int row = i >> 3, c = i & 7;
        cp16(sbase + SWZ(row * 128 + c * 16), src + (size_t)row * ld + c * 8);
    }
}

// ------------- 128x128-tile bf16 HMMA GEMM, fp32 accum, 3-stage cp.async ----
// D[m0:+128, n0:+128] = A[m,:] @ B[n,:]^T   (A: MxK k-major; B: NxK k-major)
// MODE 0: bf16 out + fp32 bias;  MODE 2: fp32 out = X + sig*(D+bias)
template <int MODE>
__global__ void __launch_bounds__(256, 2)
gemm128(const __nv_bfloat16* __restrict__ A, int lda,
        const __nv_bfloat16* __restrict__ B, int ldb,
        int K,
        __nv_bfloat16* __restrict__ outb, int ldo,
        const float* __restrict__ bias,
        const float* __restrict__ Xres, const float* __restrict__ sig,
        float* __restrict__ outf) {
    extern __shared__ char sm[];
    uint32_t base = smem_u32(sm);
    const uint32_t a_su[3] = {base, base + 16384, base + 32768};
    const uint32_t b_su[3] = {base + 49152, base + 65536, base + 81920};

    int tid = threadIdx.x, wid = tid >> 5, lane = tid & 31;
    int m0 = blockIdx.y * 128, n0 = blockIdx.x * 128;
    int wm = wid & 3, wn = wid >> 2;
    int lr = lane & 15, lc = lane >> 4;

    const __nv_bfloat16* Ab = A + (size_t)m0 * lda;
    const __nv_bfloat16* Bb = B + (size_t)n0 * ldb;

    float acc[2][8][4];
#pragma unroll
    for (int i = 0; i < 2; i++)
#pragma unroll
        for (int j = 0; j < 8; j++)
#pragma unroll
            for (int e = 0; e < 4; e++) acc[i][j][e] = 0.f;

    const int nc = K >> 6;
    load_tile_async<128>(Ab, (size_t)lda, a_su[0], tid);
    load_tile_async<128>(Bb, (size_t)ldb, b_su[0], tid);
    CP_COMMIT();
    if (nc > 1) {
        load_tile_async<128>(Ab + 64, (size_t)lda, a_su[1], tid);
        load_tile_async<128>(Bb + 64, (size_t)ldb, b_su[1], tid);
        CP_COMMIT();
    }

    for (int c = 0; c < nc; c++) {
        if (c + 2 <= nc) { CP_WAIT(1); } else { CP_WAIT(0); }
        __syncthreads();

        int buf = c % 3;
        uint32_t abase = a_su[buf], bbase = b_su[buf];
#pragma unroll
        for (int k16 = 0; k16 < 4; k16++) {
            uint32_t af[2][4];
#pragma unroll
            for (int mt = 0; mt < 2; mt++)
                ldsm_x4(af[mt], abase + SWZ((wm * 32 + mt * 16 + lr) * 128 + k16 * 32 + lc * 16));
            uint32_t bf4[4][4];
#pragma unroll
            for (int nt2 = 0; nt2 < 4; nt2++)
                ldsm_x4(bf4[nt2], bbase + SWZ((wn * 64 + nt2 * 16 + lr) * 128 + k16 * 32 + lc * 16));
#pragma unroll
            for (int mt = 0; mt < 2; mt++)
#pragma unroll
                for (int nt = 0; nt < 8; nt++)
                    mma16816(acc[mt][nt], af[mt], bf4[nt >> 1][nt & 1], bf4[nt >> 1][2 + (nt & 1)]);
        }

        if (c + 2 < nc) {
            int nb = (c + 2) % 3;
            load_tile_async<128>(Ab + (c + 2) * 64, (size_t)lda, a_su[nb], tid);
            load_tile_async<128>(Bb + (c + 2) * 64, (size_t)ldb, b_su[nb], tid);
            CP_COMMIT();
        }
    }

    int r0 = m0 + wm * 32 + (lane >> 2);
    int c0 = n0 + wn * 64 + (lane & 3) * 2;
    float s = 0.f;
    if (MODE == 2) s = sig[0];
#pragma unroll
    for (int mt = 0; mt < 2; mt++) {
#pragma unroll
        for (int half = 0; half < 2; half++) {
            int row = r0 + mt * 16 + half * 8;
#pragma unroll
            for (int nt = 0; nt < 8; nt++) {
                int col = c0 + nt * 8;
                float v0 = acc[mt][nt][half * 2 + 0];
                float v1 = acc[mt][nt][half * 2 + 1];
                if (MODE == 0) {
                    v0 += bias[col]; v1 += bias[col + 1];
                    *(__nv_bfloat162*)(outb + (size_t)row * ldo + col) =
                        __floats2bfloat162_rn(v0, v1);
                }
                if (MODE == 2) {
                    const float* xr = Xres + (size_t)row * CCH + col;
                    float2 xv = *(const float2*)xr;
                    float2 o;
                    o.x = xv.x + s * (v0 + bias[col]);
                    o.y = xv.y + s * (v1 + bias[col + 1]);
                    *(float2*)(outf + (size_t)row * CCH + col) = o;
                }
            }
        }
    }
}

// ------------- fused attention: ag = softmax(theta phi^T) g ----------------
// CTA = 64 queries; loop 16 KV chunks of 64.
// S phase: 8 warps as 4m x 2n over 64x64; PV phase: 2m x 4n over 64x256.
// SMEM: theta 8K | phi 2x8K | gT 2x32K | P 8K | wsum 512B | rinv 256B
#define ATTN_SMEM (99072)
__global__ void __launch_bounds__(256, 2) attn_fused() {
    extern __shared__ char sm[];
    uint32_t base = smem_u32(sm);
    const uint32_t th_s = base;
    const uint32_t ph_s[2] = {base + 8192, base + 16384};
    const uint32_t gt_s[2] = {base + 24576, base + 57344};
    const uint32_t p_s = base + 90112;
    float* wsum = (float*)(sm + 98304);   // [2][64]
    float* rinv = (float*)(sm + 98816);   // [64]

    int tid = threadIdx.x, wid = tid >> 5, lane = tid & 31;
    int lr = lane & 15, lc = lane >> 4;
    int mbase = blockIdx.x * 64;
    int b = blockIdx.x >> 6;
    int wm = wid & 3, wn = wid >> 2;       // S phase
    int pm = wid & 1, pn = wid >> 1;       // PV phase

    const __nv_bfloat16* thp = g_projb + (size_t)mbase * NPROJ;
    const __nv_bfloat16* php = g_phi + (size_t)b * NKV * DK;
    const __nv_bfloat16* gtp = g_gT + (size_t)b * DV * NKV;

    float O[2][8][4];
#pragma unroll
    for (int i = 0; i < 2; i++)
#pragma unroll
        for (int j = 0; j < 8; j++)
#pragma unroll
            for (int e = 0; e < 4; e++) O[i][j][e] = 0.f;
    float sum0 = 0.f, sum1 = 0.f;

    // prologue loads: theta + chunk 0
    load_tile_async<64>(thp, NPROJ, th_s, tid);
    load_tile_async<64>(php, DK, ph_s[0], tid);
    load_tile_async<256>(gtp, NKV, gt_s[0], tid);
    CP_COMMIT();

    for (int c = 0; c < 16; c++) {
        CP_WAIT(0);
        __syncthreads();   // loads for chunk c ready; PV of c-1 done by all warps

        if (c + 1 < 16) {  // prefetch c+1 (overlaps compute of c)
            int nb = (c + 1) & 1;
            load_tile_async<64>(php + (size_t)(c + 1) * 64 * DK, DK, ph_s[nb], tid);
            load_tile_async<256>(gtp + (c + 1) * 64, NKV, gt_s[nb], tid);
            CP_COMMIT();
        }

        // ---- S phase: S[64q x 64kv] = theta @ phi^T ----
        float sacc[4][4];
#pragma unroll
        for (int j = 0; j < 4; j++)
#pragma unroll
            for (int e = 0; e < 4; e++) sacc[j][e] = 0.f;
        uint32_t pb = ph_s[c & 1];
#pragma unroll
        for (int k16 = 0; k16 < 4; k16++) {
            uint32_t af[4];
            ldsm_x4(af, th_s + SWZ((wm * 16 + lr) * 128 + k16 * 32 + lc * 16));
            uint32_t bf2[2][4];
#pragma unroll
            for (int nt2 = 0; nt2 < 2; nt2++)
                ldsm_x4(bf2[nt2], pb + SWZ((wn * 32 + nt2 * 16 + lr) * 128 + k16 * 32 + lc * 16));
#pragma unroll
            for (int nt = 0; nt < 4; nt++)
                mma16816(sacc[nt], af, bf2[nt >> 1][nt & 1], bf2[nt >> 1][2 + (nt & 1)]);
        }

        // exp, accumulate row sums, store P (bf16) to SMEM
        int srow = wm * 16 + (lane >> 2);
#pragma unroll
        for (int nt = 0; nt < 4; nt++) {
            int scol = wn * 32 + nt * 8 + (lane & 3) * 2;
            float e0 = __expf(sacc[nt][0]);
            float e1 = __expf(sacc[nt][1]);
            float e2 = __expf(sacc[nt][2]);
            float e3 = __expf(sacc[nt][3]);
            sum0 += e0 + e1;
            sum1 += e2 + e3;
            *(uint32_t*)(sm + (p_s - base) + SWZ(srow * 128 + scol * 2)) =
                __nv_bfloat162_raw(__floats2bfloat162_rn(e0, e1)).x |
                ((uint32_t)__nv_bfloat162_raw(__floats2bfloat162_rn(e0, e1)).y << 16);
            // NOTE: simpler direct store below (overwrites the above cleanly)
            *(__nv_bfloat162*)(sm + (p_s - base) + SWZ(srow * 128 + scol * 2)) =
                __floats2bfloat162_rn(e0, e1);
            *(__nv_bfloat162*)(sm + (p_s - base) + SWZ((srow + 8) * 128 + scol * 2)) =
                __floats2bfloat162_rn(e2, e3);
        }
        __syncthreads();   // P complete before PV reads

        // ---- PV phase: O[64q x 256d] += P @ gT_chunk^T ----
        uint32_t gb = gt_s[c & 1];
#pragma unroll
        for (int k16 = 0; k16 < 4; k16++) {
            uint32_t paf[2][4];
#pragma unroll
            for (int mt = 0; mt < 2; mt++)
                ldsm_x4(paf[mt], p_s + SWZ((pm * 32 + mt * 16 + lr) * 128 + k16 * 32 + lc * 16));
            uint32_t gbf[4][4];
#pragma unroll
            for (int nt2 = 0; nt2 < 4; nt2++)
                ldsm_x4(gbf[nt2], gb + SWZ((pn * 64 + nt2 * 16 + lr) * 128 + k16 * 32 + lc * 16));
#pragma unroll
            for (int mt = 0; mt < 2; mt++)
#pragma unroll
                for (int nt = 0; nt < 8; nt++)
                    mma16816(O[mt][nt], paf[mt], gbf[nt >> 1][nt & 1], gbf[nt >> 1][2 + (nt & 1)]);
        }
    }

    // ---- deterministic row-sum reduction ----
    sum0 += __shfl_xor_sync(0xffffffffu, sum0, 1);
    sum0 += __shfl_xor_sync(0xffffffffu, sum0, 2);
    sum1 += __shfl_xor_sync(0xffffffffu, sum1, 1);
    sum1 += __shfl_xor_sync(0xffffffffu, sum1, 2);
    if ((lane & 3) == 0) {
        wsum[wn * 64 + wm * 16 + (lane >> 2)] = sum0;
        wsum[wn * 64 + wm * 16 + 8 + (lane >> 2)] = sum1;
    }
    __syncthreads();
    if (tid < 64) rinv[tid] = 1.f / (wsum[tid] + wsum[64 + tid]);
    __syncthreads();

    // ---- epilogue ----
#pragma unroll
    for (int mt = 0; mt < 2; mt++) {
#pragma unroll
        for (int half = 0; half < 2; half++) {
            int row = pm * 32 + mt * 16 + half * 8 + (lane >> 2);
            float rs = rinv[row];
            __nv_bfloat16* dst = g_ag + (size_t)(mbase + row) * DV;
#pragma unroll
            for (int nt = 0; nt < 8; nt++) {
                int col = pn * 64 + nt * 8 + (lane & 3) * 2;
                *(__nv_bfloat162*)(dst + col) = __floats2bfloat162_rn(
                    O[mt][nt][half * 2 + 0] * rs, O[mt][nt][half * 2 + 1] * rs);
            }
        }
    }
}

// ---------------- small kernels ----------------
__global__ void pack_kernel(const float* __restrict__ wt, const float* __restrict__ wp,
                            const float* __restrict__ wg, const float* __restrict__ bt,
                            const float* __restrict__ bp, const float* __restrict__ bg,
                            const float* __restrict__ wo) {
    int idx = blockIdx.x * blockDim.x + threadIdx.x;
    if (idx < NPROJ * CCH) {           // wcatT[n][k] = w(k, n)
        int n = idx / CCH, k = idx - n * CCH;
        float v;
        if (n < 64)       v = wt[k * 64 + n];
        else if (n < 128) v = wp[k * 64 + (n - 64)];
        else              v = wg[k * 256 + (n - 128)];
        g_wcatT[idx] = __float2bfloat16(v);
    }
    if (idx < CCH * DV) {              // woT[n][k] = wo[k][n]
        int n = idx / DV, k = idx - n * DV;
        g_woT[idx] = __float2bfloat16(wo[k * CCH + n]);
    }
    if (idx < NPROJ) {
        float v;
        if (idx < 64)       v = bt[idx];
        else if (idx < 128) v = bp[idx - 64];
        else                v = bg[idx - 128];
        g_bcat[idx] = v;
    }
}

__global__ void xconv_kernel(const float* __restrict__ x) {
    int i = blockIdx.x * blockDim.x + threadIdx.x;  // 8 elems each
    if (i >= M_PIX * CCH / 8) return;
    float4 a = *(const float4*)(x + (size_t)i * 8);
    float4 b = *(const float4*)(x + (size_t)i * 8 + 4);
    __nv_bfloat162 h[4];
    h[0] = __floats2bfloat162_rn(a.x, a.y);
    h[1] = __floats2bfloat162_rn(a.z, a.w);
    h[2] = __floats2bfloat162_rn(b.x, b.y);
    h[3] = __floats2bfloat162_rn(b.z, b.w);
    *(uint4*)(g_xb + (size_t)i * 8) = *(uint4*)h;
}

__global__ void pool_phi_kernel() {
    int i = blockIdx.x * blockDim.x + threadIdx.x;
    if (i >= BBATCH * NKV * 8) return;   // 8 groups of 8 channels
    int pp = i >> 3, c8 = i & 7;
    int b = pp >> 10, idx = pp & 1023;
    int h2 = idx >> 5, w2 = idx & 31;
    size_t p = (size_t)((b * 64 + h2 * 2) * 64 + w2 * 2);
    const __nv_bfloat16* src = g_projb + p * NPROJ + 64 + c8 * 8;
    uint4 u0 = *(const uint4*)(src);
    uint4 u1 = *(const uint4*)(src + NPROJ);
    uint4 u2 = *(const uint4*)(src + 64 * NPROJ);
    uint4 u3 = *(const uint4*)(src + 65 * NPROJ);
    __nv_bfloat162* h0 = (__nv_bfloat162*)&u0; __nv_bfloat162* h1 = (__nv_bfloat162*)&u1;
    __nv_bfloat162* h2v = (__nv_bfloat162*)&u2; __nv_bfloat162* h3 = (__nv_bfloat162*)&u3;
    __nv_bfloat162 o[4];
#pragma unroll
    for (int j = 0; j < 4; j++)
        o[j] = __hmax2(__hmax2(h0[j], h1[j]), __hmax2(h2v[j], h3[j]));
    *(uint4*)(g_phi + (size_t)pp * DK + c8 * 8) = *(uint4*)o;
}

__global__ void pool_gt_kernel() {   // pooled g, transposed to [b][d][kv]
    __shared__ __nv_bfloat16 ts[64][65];
    int tid = threadIdx.x;
    int d0 = blockIdx.x * 64, kv0 = blockIdx.y * 64, b = blockIdx.z;
#pragma unroll
    for (int e = 0; e < 16; e++) {
        int idx = tid + e * 256;
        int kvl = idx >> 6, dl = idx & 63;
        int kv = kv0 + kvl;
        int h2 = kv >> 5, w2 = kv & 31;
        size_t p = (size_t)((b * 64 + h2 * 2) * 64 + w2 * 2);
        const __nv_bfloat16* src = g_projb + p * NPROJ + 128 + d0 + dl;
        __nv_bfloat16 v = __hmax(__hmax(src[0], src[NPROJ]),
                                 __hmax(src[64 * NPROJ], src[65 * NPROJ]));
        ts[kvl][dl] = v;
    }
    __syncthreads();
#pragma unroll
    for (int e = 0; e < 16; e++) {
        int idx = tid + e * 256;
        int dl = idx >> 6, kk = idx & 63;
        g_gT[((size_t)b * DV + d0 + dl) * NKV + kv0 + kk] = ts[kk][dl];
    }
}

// ---------------- launcher ----------------
extern "C" void kernel_launch(void* const* d_in, const int* in_sizes, int n_in,
                              void* d_out, int out_size) {
    const float* x       = (const float*)d_in[0];
    const float* w_theta = (const float*)d_in[1];
    const float* b_theta = (const float*)d_in[2];
    const float* w_phi   = (const float*)d_in[3];
    const float* b_phi   = (const float*)d_in[4];
    const float* w_g     = (const float*)d_in[5];
    const float* b_g     = (const float*)d_in[6];
    const float* w_o     = (const float*)d_in[7];
    const float* b_o     = (const float*)d_in[8];
    const float* sigma   = (const float*)d_in[9];
    float* out = (float*)d_out;

    const int SMEM128 = 98304;
    cudaFuncSetAttribute((const void*)gemm128<0>, cudaFuncAttributeMaxDynamicSharedMemorySize, SMEM128);
    cudaFuncSetAttribute((const void*)gemm128<2>, cudaFuncAttributeMaxDynamicSharedMemorySize, SMEM128);
    cudaFuncSetAttribute((const void*)attn_fused, cudaFuncAttributeMaxDynamicSharedMemorySize, ATTN_SMEM);

    __nv_bfloat16 *xb, *projb, *ag, *wcatT, *woT;
    float* bcat;
    cudaGetSymbolAddress((void**)&xb, g_xb);       cudaGetSymbolAddress((void**)&projb, g_projb);
    cudaGetSymbolAddress((void**)&ag, g_ag);
    cudaGetSymbolAddress((void**)&wcatT, g_wcatT); cudaGetSymbolAddress((void**)&woT, g_woT);
    cudaGetSymbolAddress((void**)&bcat, g_bcat);

    pack_kernel<<<(NPROJ * CCH + 255) / 256, 256>>>(w_theta, w_phi, w_g,
                                                    b_theta, b_phi, b_g, w_o);
    xconv_kernel<<<M_PIX * CCH / 8 / 256, 256>>>(x);

    // proj: [65536, 384] = xb[65536,512] @ wcatT[384,512]^T, +bias
    gemm128<0><<<dim3(NPROJ / 128, M_PIX / 128), 256, SMEM128>>>(
        xb, CCH, wcatT, CCH, CCH, projb, NPROJ, bcat, nullptr, nullptr, nullptr);

    pool_phi_kernel<<<(BBATCH * NKV * 8 + 255) / 256, 256>>>();
    pool_gt_kernel<<<dim3(DV / 64, NKV / 64, BBATCH), 256>>>();

    // fused attention: ag = softmax(theta phi^T) g
    attn_fused<<<M_PIX / 64, 256, ATTN_SMEM>>>();

    // out: [65536, 512] = x + sigma * (ag[65536,256] @ woT[512,256]^T + b_o)
    gemm128<2><<<dim3(CCH / 128, M_PIX / 128), 256, SMEM128>>>(
        ag, DV, woT, DV, DV, nullptr, 0, b_o, x, sigma, out);
}

// round 7
// speedup vs baseline: 1.2097x; 1.0511x over previous
#include <cuda_runtime.h>
#include <cuda_bf16.h>
#include <cstdint>

#define BBATCH 16
#define CCH 512
#define M_PIX (BBATCH*64*64)     // 65536
#define NPROJ 384
#define DK 64
#define DV 256
#define NKV 1024
#define NQ  4096

// ---------------- scratch (device globals) ----------------
__device__ __align__(256) __nv_bfloat16 g_xb   [M_PIX * CCH];       // x in bf16
__device__ __align__(256) __nv_bfloat16 g_theta[M_PIX * DK];        // theta [q][64]
__device__ __align__(256) __nv_bfloat16 g_phi  [BBATCH * NKV * DK]; // pooled phi [kv][d]
__device__ __align__(256) __nv_bfloat16 g_gT   [BBATCH * DV * NKV]; // pooled g^T [d][kv]
__device__ __align__(256) __nv_bfloat16 g_ag   [M_PIX * DV];        // attn out bf16
__device__ __align__(256) __nv_bfloat16 g_wcatT[NPROJ * CCH];       // proj weights^T
__device__ __align__(256) __nv_bfloat16 g_woT  [CCH * DV];          // w_o^T
__device__ float g_bcat[NPROJ];

// ---------------- helpers ----------------
__device__ __forceinline__ uint32_t smem_u32(const void* p) {
    uint32_t a;
    asm("{ .reg .u64 t; cvta.to.shared.u64 t, %1; cvt.u32.u64 %0, t; }" : "=r"(a) : "l"(p));
    return a;
}
#define SWZ(o) ((o) ^ (((o) >> 3) & 0x70))

__device__ __forceinline__ void ldsm_x4(uint32_t* r, uint32_t a) {
    asm volatile("ldmatrix.sync.aligned.m8n8.x4.shared.b16 {%0,%1,%2,%3}, [%4];"
        : "=r"(r[0]), "=r"(r[1]), "=r"(r[2]), "=r"(r[3]) : "r"(a));
}
__device__ __forceinline__ void mma16816(float* d, const uint32_t* a, uint32_t b0, uint32_t b1) {
    asm volatile("mma.sync.aligned.m16n8k16.row.col.f32.bf16.bf16.f32 "
        "{%0,%1,%2,%3}, {%4,%5,%6,%7}, {%8,%9}, {%0,%1,%2,%3};"
        : "+f"(d[0]), "+f"(d[1]), "+f"(d[2]), "+f"(d[3])
        : "r"(a[0]), "r"(a[1]), "r"(a[2]), "r"(a[3]), "r"(b0), "r"(b1));
}
__device__ __forceinline__ void cp16(uint32_t sa, const void* ga) {
    asm volatile("cp.async.cg.shared.global [%0], [%1], 16;" :: "r"(sa), "l"(ga));
}
#define CP_COMMIT() asm volatile("cp.async.commit_group;" ::: "memory")
#define CP_WAIT(n)  asm volatile("cp.async.wait_group %0;" :: "n"(n) : "memory")

// load [ROWS x 64] bf16 tile (row stride ld) into swizzled SMEM via cp.async
template <int ROWS>
__device__ __forceinline__ void load_tile_async(const __nv_bfloat16* __restrict__ src,
                                                size_t ld, uint32_t sbase, int tid) {
#pragma unroll
    for (int t = 0; t < ROWS / 32; t++) {
        int i = tid + t * 256;
        int row = i >> 3, c = i & 7;
        cp16(sbase + SWZ(row * 128 + c * 16), src + (size_t)row * ld + c * 8);
    }
}

// ------------- 128x128-tile bf16 HMMA GEMM, fp32 accum, 3-stage cp.async ----
// D[m0:+128, n0:+128] = A[m,:] @ B[n,:]^T   (A: MxK k-major; B: NxK k-major)
// MODE 0: proj — theta direct + pooled phi + pooled/transposed gT (+bias)
// MODE 2: fp32 out = X + sig*(D+bias)
template <int MODE>
__global__ void __launch_bounds__(256, 2)
gemm128(const __nv_bfloat16* __restrict__ A, int lda,
        const __nv_bfloat16* __restrict__ B, int ldb,
        int K,
        const float* __restrict__ bias,
        const float* __restrict__ Xres, const float* __restrict__ sig,
        float* __restrict__ outf) {
    extern __shared__ char sm[];
    uint32_t base = smem_u32(sm);
    const uint32_t a_su[3] = {base, base + 16384, base + 32768};
    const uint32_t b_su[3] = {base + 49152, base + 65536, base + 81920};

    int tid = threadIdx.x, wid = tid >> 5, lane = tid & 31;
    int m0 = blockIdx.y * 128, n0 = blockIdx.x * 128;
    int wm = wid & 3, wn = wid >> 2;
    int lr = lane & 15, lc = lane >> 4;

    const __nv_bfloat16* Ab = A + (size_t)m0 * lda;
    const __nv_bfloat16* Bb = B + (size_t)n0 * ldb;

    float acc[2][8][4];
#pragma unroll
    for (int i = 0; i < 2; i++)
#pragma unroll
        for (int j = 0; j < 8; j++)
#pragma unroll
            for (int e = 0; e < 4; e++) acc[i][j][e] = 0.f;

    const int nc = K >> 6;
    load_tile_async<128>(Ab, (size_t)lda, a_su[0], tid);
    load_tile_async<128>(Bb, (size_t)ldb, b_su[0], tid);
    CP_COMMIT();
    if (nc > 1) {
        load_tile_async<128>(Ab + 64, (size_t)lda, a_su[1], tid);
        load_tile_async<128>(Bb + 64, (size_t)ldb, b_su[1], tid);
        CP_COMMIT();
    }

    for (int c = 0; c < nc; c++) {
        if (c + 2 <= nc) { CP_WAIT(1); } else { CP_WAIT(0); }
        __syncthreads();

        int buf = c % 3;
        uint32_t abase = a_su[buf], bbase = b_su[buf];
#pragma unroll
        for (int k16 = 0; k16 < 4; k16++) {
            uint32_t af[2][4];
#pragma unroll
            for (int mt = 0; mt < 2; mt++)
                ldsm_x4(af[mt], abase + SWZ((wm * 32 + mt * 16 + lr) * 128 + k16 * 32 + lc * 16));
            uint32_t bf4[4][4];
#pragma unroll
            for (int nt2 = 0; nt2 < 4; nt2++)
                ldsm_x4(bf4[nt2], bbase + SWZ((wn * 64 + nt2 * 16 + lr) * 128 + k16 * 32 + lc * 16));
#pragma unroll
            for (int mt = 0; mt < 2; mt++)
#pragma unroll
                for (int nt = 0; nt < 8; nt++)
                    mma16816(acc[mt][nt], af[mt], bf4[nt >> 1][nt & 1], bf4[nt >> 1][2 + (nt & 1)]);
        }

        if (c + 2 < nc) {
            int nb = (c + 2) % 3;
            load_tile_async<128>(Ab + (c + 2) * 64, (size_t)lda, a_su[nb], tid);
            load_tile_async<128>(Bb + (c + 2) * 64, (size_t)ldb, b_su[nb], tid);
            CP_COMMIT();
        }
    }

    if (MODE == 2) {
        float s = sig[0];
        int r0 = m0 + wm * 32 + (lane >> 2);
        int c0 = n0 + wn * 64 + (lane & 3) * 2;
#pragma unroll
        for (int mt = 0; mt < 2; mt++) {
#pragma unroll
            for (int half = 0; half < 2; half++) {
                int row = r0 + mt * 16 + half * 8;
#pragma unroll
                for (int nt = 0; nt < 8; nt++) {
                    int col = c0 + nt * 8;
                    const float* xr = Xres + (size_t)row * CCH + col;
                    float2 xv = *(const float2*)xr;
                    float2 o;
                    o.x = xv.x + s * (acc[mt][nt][half * 2 + 0] + bias[col]);
                    o.y = xv.y + s * (acc[mt][nt][half * 2 + 1] + bias[col + 1]);
                    *(float2*)(outf + (size_t)row * CCH + col) = o;
                }
            }
        }
    }

    if (MODE == 0) {
        // proj epilogue with fused pooling
        int b = m0 >> 12;
        int kv0 = ((m0 >> 7) & 31) * 32;   // 32 pool windows per tile
        __nv_bfloat16* st = (__nv_bfloat16*)sm;
        __syncthreads();  // all mainloop SMEM reads done before staging reuse

        if (blockIdx.x == 0) {
            // cols 0..63 = theta (wn==0 warps), cols 64..127 = phi (wn==1)
            if (wn == 0) {
#pragma unroll
                for (int mt = 0; mt < 2; mt++)
#pragma unroll
                    for (int half = 0; half < 2; half++) {
                        int row = m0 + wm * 32 + (lane >> 2) + mt * 16 + half * 8;
#pragma unroll
                        for (int nt = 0; nt < 8; nt++) {
                            int col = nt * 8 + (lane & 3) * 2;
                            *(__nv_bfloat162*)(g_theta + (size_t)row * DK + col) =
                                __floats2bfloat162_rn(acc[mt][nt][half * 2] + bias[col],
                                                      acc[mt][nt][half * 2 + 1] + bias[col + 1]);
                        }
                    }
            } else {
#pragma unroll
                for (int mt = 0; mt < 2; mt++)
#pragma unroll
                    for (int half = 0; half < 2; half++) {
                        int lrow = wm * 32 + (lane >> 2) + mt * 16 + half * 8;
#pragma unroll
                        for (int nt = 0; nt < 8; nt++) {
                            int lcol = nt * 8 + (lane & 3) * 2;   // 0..63
                            *(__nv_bfloat162*)(st + lrow * 72 + lcol) =
                                __floats2bfloat162_rn(acc[mt][nt][half * 2] + bias[64 + lcol],
                                                      acc[mt][nt][half * 2 + 1] + bias[65 + lcol]);
                        }
                    }
            }
            __syncthreads();
            // pooled phi: 32 windows x 64 channels
            int w = tid >> 3, d8 = (tid & 7) * 8;
            __align__(16) __nv_bfloat16 o[8];
#pragma unroll
            for (int j = 0; j < 8; j++) {
                int d = d8 + j;
                o[j] = __hmax(__hmax(st[(2 * w) * 72 + d], st[(2 * w + 1) * 72 + d]),
                              __hmax(st[(64 + 2 * w) * 72 + d], st[(65 + 2 * w) * 72 + d]));
            }
            *(uint4*)(g_phi + ((size_t)(b * NKV + kv0 + w)) * DK + d8) = *(uint4*)o;
        } else {
            // g columns: stage 128x128 (stride 130), pool + transpose to g_gT
#pragma unroll
            for (int mt = 0; mt < 2; mt++)
#pragma unroll
                for (int half = 0; half < 2; half++) {
                    int lrow = wm * 32 + (lane >> 2) + mt * 16 + half * 8;
#pragma unroll
                    for (int nt = 0; nt < 8; nt++) {
                        int lcol = wn * 64 + nt * 8 + (lane & 3) * 2;   // 0..127
                        *(__nv_bfloat162*)(st + lrow * 130 + lcol) =
                            __floats2bfloat162_rn(acc[mt][nt][half * 2] + bias[n0 + lcol],
                                                  acc[mt][nt][half * 2 + 1] + bias[n0 + lcol + 1]);
                    }
                }
            __syncthreads();
            int dl = tid & 127, kvh = tid >> 7;   // 128 channels x 2 kv halves
            int dg = (blockIdx.x - 1) * 128 + dl;
            __align__(16) __nv_bfloat16 o[16];
#pragma unroll
            for (int i = 0; i < 16; i++) {
                int w = kvh * 16 + i;
                o[i] = __hmax(__hmax(st[(2 * w) * 130 + dl], st[(2 * w + 1) * 130 + dl]),
                              __hmax(st[(64 + 2 * w) * 130 + dl], st[(65 + 2 * w) * 130 + dl]));
            }
            __nv_bfloat16* dst = g_gT + ((size_t)(b * DV + dg)) * NKV + kv0 + kvh * 16;
            *(uint4*)dst = ((uint4*)o)[0];
            *(uint4*)(dst + 8) = ((uint4*)o)[1];
        }
    }
}

// ------------- fused attention: ag = softmax(theta phi^T) g ----------------
// CTA = 64 queries; loop 16 KV chunks of 64.
#define ATTN_SMEM (99072)
__global__ void __launch_bounds__(256, 2) attn_fused() {
    extern __shared__ char sm[];
    uint32_t base = smem_u32(sm);
    const uint32_t th_s = base;
    const uint32_t ph_s[2] = {base + 8192, base + 16384};
    const uint32_t gt_s[2] = {base + 24576, base + 57344};
    const uint32_t p_s = base + 90112;
    float* wsum = (float*)(sm + 98304);   // [2][64]
    float* rinv = (float*)(sm + 98816);   // [64]

    int tid = threadIdx.x, wid = tid >> 5, lane = tid & 31;
    int lr = lane & 15, lc = lane >> 4;
    int mbase = blockIdx.x * 64;
    int b = blockIdx.x >> 6;
    int wm = wid & 3, wn = wid >> 2;       // S phase
    int pm = wid & 1, pn = wid >> 1;       // PV phase

    const __nv_bfloat16* thp = g_theta + (size_t)mbase * DK;
    const __nv_bfloat16* php = g_phi + (size_t)b * NKV * DK;
    const __nv_bfloat16* gtp = g_gT + (size_t)b * DV * NKV;

    float O[2][8][4];
#pragma unroll
    for (int i = 0; i < 2; i++)
#pragma unroll
        for (int j = 0; j < 8; j++)
#pragma unroll
            for (int e = 0; e < 4; e++) O[i][j][e] = 0.f;
    float sum0 = 0.f, sum1 = 0.f;

    load_tile_async<64>(thp, DK, th_s, tid);
    load_tile_async<64>(php, DK, ph_s[0], tid);
    load_tile_async<256>(gtp, NKV, gt_s[0], tid);
    CP_COMMIT();

    for (int c = 0; c < 16; c++) {
        CP_WAIT(0);
        __syncthreads();

        if (c + 1 < 16) {
            int nb = (c + 1) & 1;
            load_tile_async<64>(php + (size_t)(c + 1) * 64 * DK, DK, ph_s[nb], tid);
            load_tile_async<256>(gtp + (c + 1) * 64, NKV, gt_s[nb], tid);
            CP_COMMIT();
        }

        // ---- S phase ----
        float sacc[4][4];
#pragma unroll
        for (int j = 0; j < 4; j++)
#pragma unroll
            for (int e = 0; e < 4; e++) sacc[j][e] = 0.f;
        uint32_t pb = ph_s[c & 1];
#pragma unroll
        for (int k16 = 0; k16 < 4; k16++) {
            uint32_t af[4];
            ldsm_x4(af, th_s + SWZ((wm * 16 + lr) * 128 + k16 * 32 + lc * 16));
            uint32_t bf2[2][4];
#pragma unroll
            for (int nt2 = 0; nt2 < 2; nt2++)
                ldsm_x4(bf2[nt2], pb + SWZ((wn * 32 + nt2 * 16 + lr) * 128 + k16 * 32 + lc * 16));
#pragma unroll
            for (int nt = 0; nt < 4; nt++)
                mma16816(sacc[nt], af, bf2[nt >> 1][nt & 1], bf2[nt >> 1][2 + (nt & 1)]);
        }

        int srow = wm * 16 + (lane >> 2);
#pragma unroll
        for (int nt = 0; nt < 4; nt++) {
            int scol = wn * 32 + nt * 8 + (lane & 3) * 2;
            float e0 = __expf(sacc[nt][0]);
            float e1 = __expf(sacc[nt][1]);
            float e2 = __expf(sacc[nt][2]);
            float e3 = __expf(sacc[nt][3]);
            sum0 += e0 + e1;
            sum1 += e2 + e3;
            *(__nv_bfloat162*)(sm + (p_s - base) + SWZ(srow * 128 + scol * 2)) =
                __floats2bfloat162_rn(e0, e1);
            *(__nv_bfloat162*)(sm + (p_s - base) + SWZ((srow + 8) * 128 + scol * 2)) =
                __floats2bfloat162_rn(e2, e3);
        }
        __syncthreads();

        // ---- PV phase ----
        uint32_t gb = gt_s[c & 1];
#pragma unroll
        for (int k16 = 0; k16 < 4; k16++) {
            uint32_t paf[2][4];
#pragma unroll
            for (int mt = 0; mt < 2; mt++)
                ldsm_x4(paf[mt], p_s + SWZ((pm * 32 + mt * 16 + lr) * 128 + k16 * 32 + lc * 16));
            uint32_t gbf[4][4];
#pragma unroll
            for (int nt2 = 0; nt2 < 4; nt2++)
                ldsm_x4(gbf[nt2], gb + SWZ((pn * 64 + nt2 * 16 + lr) * 128 + k16 * 32 + lc * 16));
#pragma unroll
            for (int mt = 0; mt < 2; mt++)
#pragma unroll
                for (int nt = 0; nt < 8; nt++)
                    mma16816(O[mt][nt], paf[mt], gbf[nt >> 1][nt & 1], gbf[nt >> 1][2 + (nt & 1)]);
        }
    }

    // deterministic row-sum reduction
    sum0 += __shfl_xor_sync(0xffffffffu, sum0, 1);
    sum0 += __shfl_xor_sync(0xffffffffu, sum0, 2);
    sum1 += __shfl_xor_sync(0xffffffffu, sum1, 1);
    sum1 += __shfl_xor_sync(0xffffffffu, sum1, 2);
    if ((lane & 3) == 0) {
        wsum[wn * 64 + wm * 16 + (lane >> 2)] = sum0;
        wsum[wn * 64 + wm * 16 + 8 + (lane >> 2)] = sum1;
    }
    __syncthreads();
    if (tid < 64) rinv[tid] = 1.f / (wsum[tid] + wsum[64 + tid]);
    __syncthreads();

#pragma unroll
    for (int mt = 0; mt < 2; mt++) {
#pragma unroll
        for (int half = 0; half < 2; half++) {
            int row = pm * 32 + mt * 16 + half * 8 + (lane >> 2);
            float rs = rinv[row];
            __nv_bfloat16* dst = g_ag + (size_t)(mbase + row) * DV;
#pragma unroll
            for (int nt = 0; nt < 8; nt++) {
                int col = pn * 64 + nt * 8 + (lane & 3) * 2;
                *(__nv_bfloat162*)(dst + col) = __floats2bfloat162_rn(
                    O[mt][nt][half * 2 + 0] * rs, O[mt][nt][half * 2 + 1] * rs);
            }
        }
    }
}

// ---------------- small kernels ----------------
__global__ void pack_kernel(const float* __restrict__ wt, const float* __restrict__ wp,
                            const float* __restrict__ wg, const float* __restrict__ bt,
                            const float* __restrict__ bp, const float* __restrict__ bg,
                            const float* __restrict__ wo) {
    int idx = blockIdx.x * blockDim.x + threadIdx.x;
    if (idx < NPROJ * CCH) {           // wcatT[n][k] = w(k, n)
        int n = idx / CCH, k = idx - n * CCH;
        float v;
        if (n < 64)       v = wt[k * 64 + n];
        else if (n < 128) v = wp[k * 64 + (n - 64)];
        else              v = wg[k * 256 + (n - 128)];
        g_wcatT[idx] = __float2bfloat16(v);
    }
    if (idx < CCH * DV) {              // woT[n][k] = wo[k][n]
        int n = idx / DV, k = idx - n * DV;
        g_woT[idx] = __float2bfloat16(wo[k * CCH + n]);
    }
    if (idx < NPROJ) {
        float v;
        if (idx < 64)       v = bt[idx];
        else if (idx < 128) v = bp[idx - 64];
        else                v = bg[idx - 128];
        g_bcat[idx] = v;
    }
}

__global__ void xconv_kernel(const float* __restrict__ x) {
    int i = blockIdx.x * blockDim.x + threadIdx.x;  // 8 elems each
    if (i >= M_PIX * CCH / 8) return;
    float4 a = *(const float4*)(x + (size_t)i * 8);
    float4 b = *(const float4*)(x + (size_t)i * 8 + 4);
    __nv_bfloat162 h[4];
    h[0] = __floats2bfloat162_rn(a.x, a.y);
    h[1] = __floats2bfloat162_rn(a.z, a.w);
    h[2] = __floats2bfloat162_rn(b.x, b.y);
    h[3] = __floats2bfloat162_rn(b.z, b.w);
    *(uint4*)(g_xb + (size_t)i * 8) = *(uint4*)h;
}

// ---------------- launcher ----------------
extern "C" void kernel_launch(void* const* d_in, const int* in_sizes, int n_in,
                              void* d_out, int out_size) {
    const float* x       = (const float*)d_in[0];
    const float* w_theta = (const float*)d_in[1];
    const float* b_theta = (const float*)d_in[2];
    const float* w_phi   = (const float*)d_in[3];
    const float* b_phi   = (const float*)d_in[4];
    const float* w_g     = (const float*)d_in[5];
    const float* b_g     = (const float*)d_in[6];
    const float* w_o     = (const float*)d_in[7];
    const float* b_o     = (const float*)d_in[8];
    const float* sigma   = (const float*)d_in[9];
    float* out = (float*)d_out;

    const int SMEM128 = 98304;
    cudaFuncSetAttribute((const void*)gemm128<0>, cudaFuncAttributeMaxDynamicSharedMemorySize, SMEM128);
    cudaFuncSetAttribute((const void*)gemm128<2>, cudaFuncAttributeMaxDynamicSharedMemorySize, SMEM128);
    cudaFuncSetAttribute((const void*)attn_fused, cudaFuncAttributeMaxDynamicSharedMemorySize, ATTN_SMEM);

    __nv_bfloat16 *xb, *ag, *wcatT, *woT;
    float* bcat;
    cudaGetSymbolAddress((void**)&xb, g_xb);
    cudaGetSymbolAddress((void**)&ag, g_ag);
    cudaGetSymbolAddress((void**)&wcatT, g_wcatT);
    cudaGetSymbolAddress((void**)&woT, g_woT);
    cudaGetSymbolAddress((void**)&bcat, g_bcat);

    pack_kernel<<<(NPROJ * CCH + 255) / 256, 256>>>(w_theta, w_phi, w_g,
                                                    b_theta, b_phi, b_g, w_o);
    xconv_kernel<<<M_PIX * CCH / 8 / 256, 256>>>(x);

    // proj (+fused pooling): theta/phi/gT produced directly
    gemm128<0><<<dim3(NPROJ / 128, M_PIX / 128), 256, SMEM128>>>(
        xb, CCH, wcatT, CCH, CCH, bcat, nullptr, nullptr, nullptr);

    // fused attention: ag = softmax(theta phi^T) g
    attn_fused<<<M_PIX / 64, 256, ATTN_SMEM>>>();

    // out: [65536, 512] = x + sigma * (ag[65536,256] @ woT[512,256]^T + b_o)
    gemm128<2><<<dim3(CCH / 128, M_PIX / 128), 256, SMEM128>>>(
        ag, DV, woT, DV, DV, b_o, x, sigma, out);
}